// round 3
// baseline (speedup 1.0000x reference)
#include <cuda_runtime.h>
#include <cuda_bf16.h>

// Problem constants
#define BATCH   2
#define SEQ     2048
#define DIM     1024
#define HEADS   16
#define HDIM    64
#define ROWS    (BATCH * SEQ)          // 4096
#define ATTN_SCALE 0.125f              // 64^-0.5

// ---------------- scratch (no allocation allowed) ----------------
__device__ float g_Q[BATCH * HEADS * SEQ * HDIM];   // [bh][n][d]
__device__ float g_K[BATCH * HEADS * SEQ * HDIM];
__device__ float g_V[BATCH * HEADS * SEQ * HDIM];
__device__ float g_AO[ROWS * DIM];                  // [b*SEQ+n][dim]

// ---------------- 128x128x8 SIMT SGEMM ----------------
// C = A[ROWS x DIM] @ B[DIM x DIM]; 256 threads, 8x8 per thread.
// SPLIT_HEADS: write C into head-split layout [(b*H+h)*SEQ+n]*64+d
// else: C[row*DIM+col] = acc + bias[col]
template <int SPLIT_HEADS>
__global__ void __launch_bounds__(256)
gemm128(const float* __restrict__ A, const float* __restrict__ B,
        float* __restrict__ C, const float* __restrict__ bias)
{
    __shared__ float As[8][128];
    __shared__ float Bs[8][128];

    const int tid  = threadIdx.x;
    const int row0 = blockIdx.y * 128;
    const int col0 = blockIdx.x * 128;
    const int ty   = tid >> 4;      // 0..15
    const int tx   = tid & 15;      // 0..15

    const int a_r = tid >> 1;          // 0..127
    const int a_k = (tid & 1) * 4;     // 0 or 4
    const int b_k = tid >> 5;          // 0..7
    const int b_c = (tid & 31) * 4;    // 0..124

    float acc[8][8];
#pragma unroll
    for (int i = 0; i < 8; i++)
#pragma unroll
        for (int j = 0; j < 8; j++) acc[i][j] = 0.f;

    for (int k0 = 0; k0 < DIM; k0 += 8) {
        float4 av = *(const float4*)&A[(row0 + a_r) * DIM + k0 + a_k];
        float4 bv = *(const float4*)&B[(k0 + b_k) * DIM + col0 + b_c];
        As[a_k + 0][a_r] = av.x;
        As[a_k + 1][a_r] = av.y;
        As[a_k + 2][a_r] = av.z;
        As[a_k + 3][a_r] = av.w;
        *(float4*)&Bs[b_k][b_c] = bv;
        __syncthreads();

#pragma unroll
        for (int k = 0; k < 8; k++) {
            float a[8], b[8];
#pragma unroll
            for (int i = 0; i < 8; i++) a[i] = As[k][ty * 8 + i];
#pragma unroll
            for (int j = 0; j < 8; j++) b[j] = Bs[k][tx * 8 + j];
#pragma unroll
            for (int i = 0; i < 8; i++)
#pragma unroll
                for (int j = 0; j < 8; j++)
                    acc[i][j] += a[i] * b[j];
        }
        __syncthreads();
    }

    // epilogue
#pragma unroll
    for (int i = 0; i < 8; i++) {
        const int row = row0 + ty * 8 + i;
        if (SPLIT_HEADS) {
            const int b = row >> 11;        // /SEQ
            const int n = row & (SEQ - 1);
#pragma unroll
            for (int j = 0; j < 8; j++) {
                const int col = col0 + tx * 8 + j;
                const int h = col >> 6;
                const int d = col & 63;
                C[((b * HEADS + h) * SEQ + n) * HDIM + d] = acc[i][j];
            }
        } else {
#pragma unroll
            for (int j = 0; j < 8; j++) {
                const int col = col0 + tx * 8 + j;
                C[row * DIM + col] = acc[i][j] + bias[col];
            }
        }
    }
}

// ---------------- flash attention (fp32) ----------------
// grid: (SEQ/64, BATCH*HEADS), block 256.
// Thread owns query row r = tid&63 and 16 cols/dims group cg = tid>>6.
#define QLD 68   // padded ld for Qs/Ps: aligned float4, conflict-free

__global__ void __launch_bounds__(256)
attn_kernel(const float* __restrict__ Q, const float* __restrict__ K,
            const float* __restrict__ V, float* __restrict__ AO)
{
    extern __shared__ float sm[];
    float* Qs     = sm;                    // 64*QLD
    float* Ks     = Qs + 64 * QLD;         // 64*64
    float* Vs     = Ks + 64 * 64;          // 64*64
    float* Ps     = Vs + 64 * 64;          // 64*QLD
    float* redmax = Ps + 64 * QLD;         // 256
    float* redsum = redmax + 256;          // 256

    const int tid = threadIdx.x;
    const int r   = tid & 63;
    const int cg  = tid >> 6;      // 0..3
    const int c0  = cg * 16;
    const int bh  = blockIdx.y;
    const int q0  = blockIdx.x * 64;

    const float* Qg = Q + (size_t)(bh * SEQ + q0) * HDIM;
    const float* Kg = K + (size_t)bh * SEQ * HDIM;
    const float* Vg = V + (size_t)bh * SEQ * HDIM;

    // load Q tile (once)
    for (int i = tid; i < 64 * 64; i += 256) {
        int m = i >> 6, d = i & 63;
        Qs[m * QLD + d] = Qg[m * HDIM + d];
    }

    float mrow = -1e30f, lrow = 0.f;
    float o[16];
#pragma unroll
    for (int j = 0; j < 16; j++) o[j] = 0.f;

    for (int kt = 0; kt < SEQ; kt += 64) {
        __syncthreads();   // protect Ks/Vs/Ps from previous-iter readers (also covers Qs first iter)

        // load K/V tiles, vectorized
        for (int i = tid; i < 64 * 16; i += 256) {
            int m = i >> 4;
            int d = (i & 15) * 4;
            *(float4*)&Ks[m * 64 + d] = *(const float4*)&Kg[(kt + m) * HDIM + d];
            *(float4*)&Vs[m * 64 + d] = *(const float4*)&Vg[(kt + m) * HDIM + d];
        }
        __syncthreads();

        // ---- S = Q K^T * scale ----
        float s[16];
#pragma unroll
        for (int j = 0; j < 16; j++) s[j] = 0.f;
#pragma unroll
        for (int k4 = 0; k4 < 64; k4 += 4) {
            float4 qv = *(const float4*)&Qs[r * QLD + k4];
#pragma unroll
            for (int j = 0; j < 16; j++) {
                float4 kv = *(const float4*)&Ks[(c0 + j) * 64 + k4];
                s[j] += qv.x * kv.x + qv.y * kv.y + qv.z * kv.z + qv.w * kv.w;
            }
        }
#pragma unroll
        for (int j = 0; j < 16; j++) s[j] *= ATTN_SCALE;

        // ---- online softmax ----
        float pmax = s[0];
#pragma unroll
        for (int j = 1; j < 16; j++) pmax = fmaxf(pmax, s[j]);
        redmax[cg * 64 + r] = pmax;
        __syncthreads();

        float mt = fmaxf(fmaxf(redmax[r], redmax[64 + r]),
                         fmaxf(redmax[128 + r], redmax[192 + r]));
        float mnew  = fmaxf(mrow, mt);
        float alpha = __expf(mrow - mnew);

        float psum = 0.f;
#pragma unroll
        for (int j = 0; j < 16; j++) {
            float p = __expf(s[j] - mnew);
            psum += p;
            Ps[r * QLD + c0 + j] = p;
        }
        redsum[cg * 64 + r] = psum;
        __syncthreads();

        lrow = lrow * alpha + (redsum[r] + redsum[64 + r] +
                               redsum[128 + r] + redsum[192 + r]);
        mrow = mnew;

        // ---- O = O*alpha + P V ----
#pragma unroll
        for (int j = 0; j < 16; j++) o[j] *= alpha;
#pragma unroll
        for (int m4 = 0; m4 < 64; m4 += 4) {
            float4 pv = *(const float4*)&Ps[r * QLD + m4];
#pragma unroll
            for (int mm = 0; mm < 4; mm++) {
                float p = (mm == 0) ? pv.x : (mm == 1) ? pv.y : (mm == 2) ? pv.z : pv.w;
                const float* vrow = &Vs[(m4 + mm) * 64 + c0];
#pragma unroll
                for (int j4 = 0; j4 < 16; j4 += 4) {
                    float4 vv = *(const float4*)&vrow[j4];
                    o[j4 + 0] += p * vv.x;
                    o[j4 + 1] += p * vv.y;
                    o[j4 + 2] += p * vv.z;
                    o[j4 + 3] += p * vv.w;
                }
            }
        }
    }

    // epilogue: normalize + write to [b][n][h*64+d] layout
    const float inv_l = 1.0f / lrow;
    const int b = bh >> 4;
    const int h = bh & 15;
    const int n = q0 + r;
    float* dst = &g_AO[((size_t)(b * SEQ + n)) * DIM + h * HDIM + c0];
#pragma unroll
    for (int j4 = 0; j4 < 16; j4 += 4) {
        float4 v;
        v.x = o[j4 + 0] * inv_l;
        v.y = o[j4 + 1] * inv_l;
        v.z = o[j4 + 2] * inv_l;
        v.w = o[j4 + 3] * inv_l;
        *(float4*)&dst[j4] = v;
    }
}

// ---------------- launch ----------------
extern "C" void kernel_launch(void* const* d_in, const int* in_sizes, int n_in,
                              void* d_out, int out_size)
{
    const float* x  = (const float*)d_in[0];
    const float* y  = (const float*)d_in[1];
    const float* Wq = (const float*)d_in[2];
    const float* Wk = (const float*)d_in[3];
    const float* Wv = (const float*)d_in[4];
    const float* Wp = (const float*)d_in[5];
    const float* bp = (const float*)d_in[6];
    float* out = (float*)d_out;

    float *qb, *kb, *vb, *ao;
    cudaGetSymbolAddress((void**)&qb, g_Q);
    cudaGetSymbolAddress((void**)&kb, g_K);
    cudaGetSymbolAddress((void**)&vb, g_V);
    cudaGetSymbolAddress((void**)&ao, g_AO);

    dim3 ggrid(DIM / 128, ROWS / 128);     // (8, 32)
    gemm128<1><<<ggrid, 256>>>(x, Wq, qb, nullptr);
    gemm128<1><<<ggrid, 256>>>(y, Wk, kb, nullptr);
    gemm128<1><<<ggrid, 256>>>(y, Wv, vb, nullptr);

    const int smem = (64 * QLD + 64 * 64 + 64 * 64 + 64 * QLD + 512) * sizeof(float);
    cudaFuncSetAttribute(attn_kernel, cudaFuncAttributeMaxDynamicSharedMemorySize, smem);
    dim3 agrid(SEQ / 64, BATCH * HEADS);   // (32, 32)
    attn_kernel<<<agrid, 256, smem>>>(qb, kb, vb, ao);

    gemm128<0><<<ggrid, 256>>>(ao, Wp, out, bp);
}

// round 8
// speedup vs baseline: 3.3520x; 3.3520x over previous
#include <cuda_runtime.h>
#include <cuda_bf16.h>

// Problem constants
#define BATCH   2
#define SEQ     2048
#define DIM     1024
#define HEADS   16
#define HDIM    64
#define ROWS    (BATCH * SEQ)          // 4096
#define ATTN_SCALE 0.125f              // 64^-0.5

// ---------------- scratch ----------------
__device__ float g_Q[BATCH * HEADS * SEQ * HDIM];   // [bh][n][d]
__device__ float g_K[BATCH * HEADS * SEQ * HDIM];
__device__ float g_V[BATCH * HEADS * SEQ * HDIM];
__device__ float g_AO[ROWS * DIM];                  // [b*SEQ+n][dim]

// ---------------- tf32 helpers ----------------
__device__ __forceinline__ float tf32r(float x) {
    unsigned u;
    asm("cvt.rna.tf32.f32 %0, %1;" : "=r"(u) : "f"(x));
    return __uint_as_float(u);
}

__device__ __forceinline__ void mma_tf32(float c[4],
                                         unsigned a0, unsigned a1, unsigned a2, unsigned a3,
                                         unsigned b0, unsigned b1)
{
    asm("mma.sync.aligned.m16n8k8.row.col.f32.tf32.tf32.f32 "
        "{%0,%1,%2,%3}, {%4,%5,%6,%7}, {%8,%9}, {%0,%1,%2,%3};"
        : "+f"(c[0]), "+f"(c[1]), "+f"(c[2]), "+f"(c[3])
        : "r"(a0), "r"(a1), "r"(a2), "r"(a3), "r"(b0), "r"(b1));
}

struct GemmPtrs {
    const float* A[3];
    const float* B[3];
    float*       C[3];
};

// ---------------- tf32 tensor-core GEMM ----------------
// C[ROWS x DIM] = A[ROWS x DIM] @ B[DIM x DIM]  (+bias / head-split epilogue)
// Block tile 128x128, BK=32, 8 warps (warp_m = warp&3 -> 32 rows, warp_n = warp>>2 -> 64 cols).
// Register-prefetch double buffering: next k-tile's LDGs issued before the mma block.
// blockIdx.z selects the (A,B,C) triple (z-batched QKV projection).
template <int SPLIT_HEADS>
__global__ void __launch_bounds__(256, 1)
gemm_tc(GemmPtrs p, const float* __restrict__ bias)
{
    __shared__ float As[128][36];
    __shared__ float Bs[32][132];

    const float* __restrict__ A = p.A[blockIdx.z];
    const float* __restrict__ B = p.B[blockIdx.z];
    float* __restrict__ C       = p.C[blockIdx.z];

    const int tid  = threadIdx.x;
    const int warp = tid >> 5;
    const int lane = tid & 31;
    const int r    = lane >> 2;       // 0..7
    const int c    = lane & 3;        // 0..3
    const int wm   = (warp & 3) * 32;
    const int wn   = (warp >> 2) * 64;
    const int row0 = blockIdx.y * 128;
    const int col0 = blockIdx.x * 128;

    // per-thread load coordinates (fixed across k-tiles)
    int am[4], ak[4], bk[4], bn[4];
#pragma unroll
    for (int j = 0; j < 4; j++) {
        int id = tid + j * 256;
        am[j] = id >> 3;          ak[j] = (id & 7) * 4;
        bk[j] = id >> 5;          bn[j] = (id & 31) * 4;
    }

    float acc[2][8][4];
#pragma unroll
    for (int i = 0; i < 2; i++)
#pragma unroll
        for (int j = 0; j < 8; j++)
#pragma unroll
            for (int t = 0; t < 4; t++) acc[i][j][t] = 0.f;

    // prologue: prefetch k-tile 0
    float4 pa[4], pb[4];
#pragma unroll
    for (int j = 0; j < 4; j++) {
        pa[j] = *(const float4*)&A[(size_t)(row0 + am[j]) * DIM + ak[j]];
        pb[j] = *(const float4*)&B[(size_t)bk[j] * DIM + col0 + bn[j]];
    }

    for (int k0 = 0; k0 < DIM; k0 += 32) {
        // commit prefetched tile to smem (cvt.rna to tf32 here)
#pragma unroll
        for (int j = 0; j < 4; j++) {
            float4 v = pa[j];
            v.x = tf32r(v.x); v.y = tf32r(v.y); v.z = tf32r(v.z); v.w = tf32r(v.w);
            *(float4*)&As[am[j]][ak[j]] = v;
            float4 w = pb[j];
            w.x = tf32r(w.x); w.y = tf32r(w.y); w.z = tf32r(w.z); w.w = tf32r(w.w);
            *(float4*)&Bs[bk[j]][bn[j]] = w;
        }
        __syncthreads();

        // prefetch next k-tile while mma block runs
        if (k0 + 32 < DIM) {
#pragma unroll
            for (int j = 0; j < 4; j++) {
                pa[j] = *(const float4*)&A[(size_t)(row0 + am[j]) * DIM + (k0 + 32) + ak[j]];
                pb[j] = *(const float4*)&B[(size_t)(k0 + 32 + bk[j]) * DIM + col0 + bn[j]];
            }
        }

#pragma unroll
        for (int ks = 0; ks < 4; ks++) {
            const int kb = ks * 8;
            unsigned a[2][4];
#pragma unroll
            for (int i = 0; i < 2; i++) {
                a[i][0] = __float_as_uint(As[wm + i * 16 + r    ][kb + c    ]);
                a[i][1] = __float_as_uint(As[wm + i * 16 + r + 8][kb + c    ]);
                a[i][2] = __float_as_uint(As[wm + i * 16 + r    ][kb + c + 4]);
                a[i][3] = __float_as_uint(As[wm + i * 16 + r + 8][kb + c + 4]);
            }
#pragma unroll
            for (int j = 0; j < 8; j++) {
                unsigned b0 = __float_as_uint(Bs[kb + c    ][wn + j * 8 + r]);
                unsigned b1 = __float_as_uint(Bs[kb + c + 4][wn + j * 8 + r]);
                mma_tf32(acc[0][j], a[0][0], a[0][1], a[0][2], a[0][3], b0, b1);
                mma_tf32(acc[1][j], a[1][0], a[1][1], a[1][2], a[1][3], b0, b1);
            }
        }
        __syncthreads();
    }

    // epilogue
#pragma unroll
    for (int i = 0; i < 2; i++) {
#pragma unroll
        for (int j = 0; j < 8; j++) {
            const int mlo = row0 + wm + i * 16 + r;
            const int mhi = mlo + 8;
            const int col = col0 + wn + j * 8 + c * 2;
            if (SPLIT_HEADS) {
                const int h = col >> 6, d = col & 63;
                {
                    const int b = mlo >> 11, n = mlo & (SEQ - 1);
                    float* dst = &C[(((size_t)(b * HEADS + h) * SEQ + n) * HDIM) + d];
                    *(float2*)dst = make_float2(acc[i][j][0], acc[i][j][1]);
                }
                {
                    const int b = mhi >> 11, n = mhi & (SEQ - 1);
                    float* dst = &C[(((size_t)(b * HEADS + h) * SEQ + n) * HDIM) + d];
                    *(float2*)dst = make_float2(acc[i][j][2], acc[i][j][3]);
                }
            } else {
                const float b0 = bias[col], b1 = bias[col + 1];
                *(float2*)&C[(size_t)mlo * DIM + col] =
                    make_float2(acc[i][j][0] + b0, acc[i][j][1] + b1);
                *(float2*)&C[(size_t)mhi * DIM + col] =
                    make_float2(acc[i][j][2] + b0, acc[i][j][3] + b1);
            }
        }
    }
}

// ---------------- tf32 tensor-core flash attention ----------------
// grid: (SEQ/64, BATCH*HEADS), 128 threads (4 warps). Warp owns 16 q rows.
// Q fragments live in registers for the whole kernel. Online softmax is
// warp-local (quad shfl only). P goes through smem for the PV mma.
#define SLD 68   // padded row stride for Ks/Vs/Ps

__global__ void __launch_bounds__(128)
attn_tc(const float* __restrict__ Q, const float* __restrict__ K,
        const float* __restrict__ V, float* __restrict__ AO)
{
    extern __shared__ float sm[];
    float* Ks = sm;                 // 64*SLD
    float* Vs = Ks + 64 * SLD;      // 64*SLD
    float* Ps = Vs + 64 * SLD;      // 64*SLD

    const int tid  = threadIdx.x;
    const int warp = tid >> 5;
    const int lane = tid & 31;
    const int r    = lane >> 2;     // 0..7
    const int c    = lane & 3;      // 0..3
    const int wr   = warp * 16;     // warp's q-row base within tile
    const int bh   = blockIdx.y;
    const int q0   = blockIdx.x * 64;

    const float* Qg = Q + ((size_t)bh * SEQ + q0) * HDIM;
    const float* Kg = K + (size_t)bh * SEQ * HDIM;
    const float* Vg = V + (size_t)bh * SEQ * HDIM;

    // Q fragments (scale folded in), held in registers: 8 ksteps x 4 regs
    unsigned qf[8][4];
#pragma unroll
    for (int ks = 0; ks < 8; ks++) {
        const int kb = ks * 8;
        qf[ks][0] = __float_as_uint(tf32r(Qg[(wr + r    ) * HDIM + kb + c    ] * ATTN_SCALE));
        qf[ks][1] = __float_as_uint(tf32r(Qg[(wr + r + 8) * HDIM + kb + c    ] * ATTN_SCALE));
        qf[ks][2] = __float_as_uint(tf32r(Qg[(wr + r    ) * HDIM + kb + c + 4] * ATTN_SCALE));
        qf[ks][3] = __float_as_uint(tf32r(Qg[(wr + r + 8) * HDIM + kb + c + 4] * ATTN_SCALE));
    }

    float m_lo = -1e30f, m_hi = -1e30f, l_lo = 0.f, l_hi = 0.f;
    float o[8][4];
#pragma unroll
    for (int nt = 0; nt < 8; nt++)
#pragma unroll
        for (int t = 0; t < 4; t++) o[nt][t] = 0.f;

    for (int kt = 0; kt < SEQ; kt += 64) {
        __syncthreads();   // protect Ks/Vs from previous-iteration readers
        // load K/V tile (64x64), cvt to tf32
#pragma unroll
        for (int j = 0; j < 8; j++) {
            int id  = tid + j * 128;
            int row = id >> 4;
            int col = (id & 15) * 4;
            float4 kv = *(const float4*)&Kg[(size_t)(kt + row) * HDIM + col];
            float4 vv = *(const float4*)&Vg[(size_t)(kt + row) * HDIM + col];
            kv.x = tf32r(kv.x); kv.y = tf32r(kv.y); kv.z = tf32r(kv.z); kv.w = tf32r(kv.w);
            vv.x = tf32r(vv.x); vv.y = tf32r(vv.y); vv.z = tf32r(vv.z); vv.w = tf32r(vv.w);
            *(float4*)&Ks[row * SLD + col] = kv;
            *(float4*)&Vs[row * SLD + col] = vv;
        }
        __syncthreads();

        // ---- S = (Q*scale) K^T via mma ----
        float s[8][4];
#pragma unroll
        for (int nt = 0; nt < 8; nt++)
#pragma unroll
            for (int t = 0; t < 4; t++) s[nt][t] = 0.f;

#pragma unroll
        for (int ks = 0; ks < 8; ks++) {
            const int kb = ks * 8;
#pragma unroll
            for (int nt = 0; nt < 8; nt++) {
                unsigned b0 = __float_as_uint(Ks[(nt * 8 + r) * SLD + kb + c    ]);
                unsigned b1 = __float_as_uint(Ks[(nt * 8 + r) * SLD + kb + c + 4]);
                mma_tf32(s[nt], qf[ks][0], qf[ks][1], qf[ks][2], qf[ks][3], b0, b1);
            }
        }

        // ---- online softmax (warp-local: quad shuffle) ----
        float tl = -1e30f, th = -1e30f;
#pragma unroll
        for (int nt = 0; nt < 8; nt++) {
            tl = fmaxf(tl, fmaxf(s[nt][0], s[nt][1]));
            th = fmaxf(th, fmaxf(s[nt][2], s[nt][3]));
        }
        tl = fmaxf(tl, __shfl_xor_sync(0xffffffffu, tl, 1));
        tl = fmaxf(tl, __shfl_xor_sync(0xffffffffu, tl, 2));
        th = fmaxf(th, __shfl_xor_sync(0xffffffffu, th, 1));
        th = fmaxf(th, __shfl_xor_sync(0xffffffffu, th, 2));

        const float ml2 = fmaxf(m_lo, tl);
        const float mh2 = fmaxf(m_hi, th);
        const float al  = __expf(m_lo - ml2);
        const float ah  = __expf(m_hi - mh2);

        float pl = 0.f, ph = 0.f;
#pragma unroll
        for (int nt = 0; nt < 8; nt++) {
            float p0 = __expf(s[nt][0] - ml2);
            float p1 = __expf(s[nt][1] - ml2);
            float p2 = __expf(s[nt][2] - mh2);
            float p3 = __expf(s[nt][3] - mh2);
            pl += p0 + p1;
            ph += p2 + p3;
            *(float2*)&Ps[(wr + r    ) * SLD + nt * 8 + c * 2] =
                make_float2(tf32r(p0), tf32r(p1));
            *(float2*)&Ps[(wr + r + 8) * SLD + nt * 8 + c * 2] =
                make_float2(tf32r(p2), tf32r(p3));
        }
        pl += __shfl_xor_sync(0xffffffffu, pl, 1);
        pl += __shfl_xor_sync(0xffffffffu, pl, 2);
        ph += __shfl_xor_sync(0xffffffffu, ph, 1);
        ph += __shfl_xor_sync(0xffffffffu, ph, 2);

        l_lo = l_lo * al + pl;  m_lo = ml2;
        l_hi = l_hi * ah + ph;  m_hi = mh2;

#pragma unroll
        for (int nt = 0; nt < 8; nt++) {
            o[nt][0] *= al; o[nt][1] *= al;
            o[nt][2] *= ah; o[nt][3] *= ah;
        }
        __syncwarp();   // P strip is warp-private: warp-level sync suffices

        // ---- O += P V via mma ----
#pragma unroll
        for (int ks = 0; ks < 8; ks++) {
            const int kb = ks * 8;
            unsigned pa0 = __float_as_uint(Ps[(wr + r    ) * SLD + kb + c    ]);
            unsigned pa1 = __float_as_uint(Ps[(wr + r + 8) * SLD + kb + c    ]);
            unsigned pa2 = __float_as_uint(Ps[(wr + r    ) * SLD + kb + c + 4]);
            unsigned pa3 = __float_as_uint(Ps[(wr + r + 8) * SLD + kb + c + 4]);
#pragma unroll
            for (int nt = 0; nt < 8; nt++) {
                unsigned b0 = __float_as_uint(Vs[(kb + c    ) * SLD + nt * 8 + r]);
                unsigned b1 = __float_as_uint(Vs[(kb + c + 4) * SLD + nt * 8 + r]);
                mma_tf32(o[nt], pa0, pa1, pa2, pa3, b0, b1);
            }
        }
    }

    // epilogue: normalize, write [b][n][h*64+d]
    const float il = 1.0f / l_lo;
    const float ih = 1.0f / l_hi;
    const int b = bh >> 4;
    const int h = bh & 15;
    const int rlo = q0 + wr + r;
    const int rhi = rlo + 8;
    float* dlo = &g_AO[((size_t)(b * SEQ + rlo)) * DIM + h * HDIM];
    float* dhi = &g_AO[((size_t)(b * SEQ + rhi)) * DIM + h * HDIM];
#pragma unroll
    for (int nt = 0; nt < 8; nt++) {
        const int d0 = nt * 8 + c * 2;
        *(float2*)&dlo[d0] = make_float2(o[nt][0] * il, o[nt][1] * il);
        *(float2*)&dhi[d0] = make_float2(o[nt][2] * ih, o[nt][3] * ih);
    }
}

// ---------------- launch ----------------
extern "C" void kernel_launch(void* const* d_in, const int* in_sizes, int n_in,
                              void* d_out, int out_size)
{
    const float* x  = (const float*)d_in[0];
    const float* y  = (const float*)d_in[1];
    const float* Wq = (const float*)d_in[2];
    const float* Wk = (const float*)d_in[3];
    const float* Wv = (const float*)d_in[4];
    const float* Wp = (const float*)d_in[5];
    const float* bp = (const float*)d_in[6];
    float* out = (float*)d_out;

    float *qb, *kb, *vb, *ao;
    cudaGetSymbolAddress((void**)&qb, g_Q);
    cudaGetSymbolAddress((void**)&kb, g_K);
    cudaGetSymbolAddress((void**)&vb, g_V);
    cudaGetSymbolAddress((void**)&ao, g_AO);

    // QKV projections: one z-batched launch (z=0: x@Wq, z=1: y@Wk, z=2: y@Wv)
    GemmPtrs qkv;
    qkv.A[0] = x;  qkv.A[1] = y;  qkv.A[2] = y;
    qkv.B[0] = Wq; qkv.B[1] = Wk; qkv.B[2] = Wv;
    qkv.C[0] = qb; qkv.C[1] = kb; qkv.C[2] = vb;
    dim3 qkv_grid(DIM / 128, ROWS / 128, 3);   // (8, 32, 3) = 768 CTAs
    gemm_tc<1><<<qkv_grid, 256>>>(qkv, nullptr);

    const int smem = 3 * 64 * SLD * sizeof(float);   // 52224 bytes
    cudaFuncSetAttribute(attn_tc, cudaFuncAttributeMaxDynamicSharedMemorySize, smem);
    dim3 agrid(SEQ / 64, BATCH * HEADS);   // (32, 32)
    attn_tc<<<agrid, 128, smem>>>(qb, kb, vb, ao);

    // output projection
    GemmPtrs po;
    po.A[0] = ao; po.B[0] = Wp; po.C[0] = out;
    po.A[1] = po.A[2] = nullptr; po.B[1] = po.B[2] = nullptr; po.C[1] = po.C[2] = nullptr;
    dim3 ogrid(DIM / 128, ROWS / 128, 1);
    gemm_tc<0><<<ogrid, 256>>>(po, bp);
}

// round 9
// speedup vs baseline: 3.7629x; 1.1226x over previous
#include <cuda_runtime.h>
#include <cuda_bf16.h>

// Problem constants
#define BATCH   2
#define SEQ     2048
#define DIM     1024
#define HEADS   16
#define HDIM    64
#define ROWS    (BATCH * SEQ)          // 4096
#define ATTN_SCALE 0.125f              // 64^-0.5

// ---------------- scratch ----------------
__device__ float g_Q[BATCH * HEADS * SEQ * HDIM];   // [bh][n][d]
__device__ float g_K[BATCH * HEADS * SEQ * HDIM];
__device__ float g_V[BATCH * HEADS * SEQ * HDIM];
__device__ float g_AO[ROWS * DIM];                  // [b*SEQ+n][dim]

// ---------------- tf32 helpers ----------------
__device__ __forceinline__ float tf32r(float x) {
    unsigned u;
    asm("cvt.rna.tf32.f32 %0, %1;" : "=r"(u) : "f"(x));
    return __uint_as_float(u);
}
// fp32 (raw, from smem) -> tf32 bit pattern for mma operand
__device__ __forceinline__ unsigned tf32b(float x) {
    unsigned u;
    asm("cvt.rna.tf32.f32 %0, %1;" : "=r"(u) : "f"(x));
    return u;
}

__device__ __forceinline__ void mma_tf32(float c[4],
                                         unsigned a0, unsigned a1, unsigned a2, unsigned a3,
                                         unsigned b0, unsigned b1)
{
    asm("mma.sync.aligned.m16n8k8.row.col.f32.tf32.tf32.f32 "
        "{%0,%1,%2,%3}, {%4,%5,%6,%7}, {%8,%9}, {%0,%1,%2,%3};"
        : "+f"(c[0]), "+f"(c[1]), "+f"(c[2]), "+f"(c[3])
        : "r"(a0), "r"(a1), "r"(a2), "r"(a3), "r"(b0), "r"(b1));
}

// ---------------- cp.async helpers ----------------
__device__ __forceinline__ void cp_async16(void* smem_ptr, const void* gmem_ptr) {
    unsigned saddr = (unsigned)__cvta_generic_to_shared(smem_ptr);
    asm volatile("cp.async.ca.shared.global [%0], [%1], 16;"
                 :: "r"(saddr), "l"(gmem_ptr));
}
#define CP_COMMIT() asm volatile("cp.async.commit_group;" ::: "memory")
#define CP_WAIT1()  asm volatile("cp.async.wait_group 1;" ::: "memory")

struct GemmPtrs {
    const float* A[3];
    const float* B[3];
    float*       C[3];
};

// ---------------- tf32 tensor-core GEMM ----------------
// C[ROWS x DIM] = A[ROWS x DIM] @ B[DIM x DIM]  (+bias / head-split epilogue)
// Block tile 128x128, BK=32, 8 warps (warp_m = warp&3 -> 32 rows, warp_n = warp>>2 -> 64 cols).
// 2-stage cp.async smem double buffer; raw fp32 in smem, cvt.rna at fragment
// load (numerically identical to converting on the store side).
// __launch_bounds__(256,2): <=128 regs -> 2 CTAs/SM.
// Dynamic smem: As[2][128][36] + Bs[2][32][132] = 70656 bytes.
#define AS_STAGE (128 * 36)
#define BS_STAGE (32 * 132)
#define GEMM_SMEM ((2 * AS_STAGE + 2 * BS_STAGE) * (int)sizeof(float))

template <int SPLIT_HEADS>
__global__ void __launch_bounds__(256, 2)
gemm_tc(GemmPtrs p, const float* __restrict__ bias)
{
    extern __shared__ float smem_g[];
    float* As = smem_g;                  // [2][128][36]
    float* Bs = smem_g + 2 * AS_STAGE;   // [2][32][132]

    const float* __restrict__ A = p.A[blockIdx.z];
    const float* __restrict__ B = p.B[blockIdx.z];
    float* __restrict__ C       = p.C[blockIdx.z];

    const int tid  = threadIdx.x;
    const int warp = tid >> 5;
    const int lane = tid & 31;
    const int r    = lane >> 2;       // 0..7
    const int c    = lane & 3;        // 0..3
    const int wm   = (warp & 3) * 32;
    const int wn   = (warp >> 2) * 64;
    const int row0 = blockIdx.y * 128;
    const int col0 = blockIdx.x * 128;

    // per-thread load coordinates (fixed across k-tiles)
    int am[4], ak[4], bk[4], bn[4];
#pragma unroll
    for (int j = 0; j < 4; j++) {
        int id = tid + j * 256;
        am[j] = id >> 3;          ak[j] = (id & 7) * 4;
        bk[j] = id >> 5;          bn[j] = (id & 31) * 4;
    }

    float acc[2][8][4];
#pragma unroll
    for (int i = 0; i < 2; i++)
#pragma unroll
        for (int j = 0; j < 8; j++)
#pragma unroll
            for (int t = 0; t < 4; t++) acc[i][j][t] = 0.f;

    const int NT = DIM / 32;   // 32 k-tiles

    // prologue: async-load k-tiles 0 and 1
#pragma unroll
    for (int s = 0; s < 2; s++) {
#pragma unroll
        for (int j = 0; j < 4; j++) {
            cp_async16(&As[s * AS_STAGE + am[j] * 36 + ak[j]],
                       &A[(size_t)(row0 + am[j]) * DIM + s * 32 + ak[j]]);
            cp_async16(&Bs[s * BS_STAGE + bk[j] * 132 + bn[j]],
                       &B[(size_t)(s * 32 + bk[j]) * DIM + col0 + bn[j]]);
        }
        CP_COMMIT();
    }

    for (int kt = 0; kt < NT; kt++) {
        const int st = kt & 1;
        CP_WAIT1();            // this tile's group complete
        __syncthreads();       // make it visible block-wide

        const float* Asb = &As[st * AS_STAGE];
        const float* Bsb = &Bs[st * BS_STAGE];

#pragma unroll
        for (int ks = 0; ks < 4; ks++) {
            const int kb = ks * 8;
            unsigned a[2][4];
#pragma unroll
            for (int i = 0; i < 2; i++) {
                a[i][0] = tf32b(Asb[(wm + i * 16 + r    ) * 36 + kb + c    ]);
                a[i][1] = tf32b(Asb[(wm + i * 16 + r + 8) * 36 + kb + c    ]);
                a[i][2] = tf32b(Asb[(wm + i * 16 + r    ) * 36 + kb + c + 4]);
                a[i][3] = tf32b(Asb[(wm + i * 16 + r + 8) * 36 + kb + c + 4]);
            }
#pragma unroll
            for (int j = 0; j < 8; j++) {
                unsigned b0 = tf32b(Bsb[(kb + c    ) * 132 + wn + j * 8 + r]);
                unsigned b1 = tf32b(Bsb[(kb + c + 4) * 132 + wn + j * 8 + r]);
                mma_tf32(acc[0][j], a[0][0], a[0][1], a[0][2], a[0][3], b0, b1);
                mma_tf32(acc[1][j], a[1][0], a[1][1], a[1][2], a[1][3], b0, b1);
            }
        }
        __syncthreads();       // all warps done with buffer st before refill

        if (kt + 2 < NT) {
            const int k0 = (kt + 2) * 32;
#pragma unroll
            for (int j = 0; j < 4; j++) {
                cp_async16(&As[st * AS_STAGE + am[j] * 36 + ak[j]],
                           &A[(size_t)(row0 + am[j]) * DIM + k0 + ak[j]]);
                cp_async16(&Bs[st * BS_STAGE + bk[j] * 132 + bn[j]],
                           &B[(size_t)(k0 + bk[j]) * DIM + col0 + bn[j]]);
            }
        }
        CP_COMMIT();           // commit every iter (empty group near the end)
    }

    // epilogue
#pragma unroll
    for (int i = 0; i < 2; i++) {
#pragma unroll
        for (int j = 0; j < 8; j++) {
            const int mlo = row0 + wm + i * 16 + r;
            const int mhi = mlo + 8;
            const int col = col0 + wn + j * 8 + c * 2;
            if (SPLIT_HEADS) {
                const int h = col >> 6, d = col & 63;
                {
                    const int b = mlo >> 11, n = mlo & (SEQ - 1);
                    float* dst = &C[(((size_t)(b * HEADS + h) * SEQ + n) * HDIM) + d];
                    *(float2*)dst = make_float2(acc[i][j][0], acc[i][j][1]);
                }
                {
                    const int b = mhi >> 11, n = mhi & (SEQ - 1);
                    float* dst = &C[(((size_t)(b * HEADS + h) * SEQ + n) * HDIM) + d];
                    *(float2*)dst = make_float2(acc[i][j][2], acc[i][j][3]);
                }
            } else {
                const float b0 = bias[col], b1 = bias[col + 1];
                *(float2*)&C[(size_t)mlo * DIM + col] =
                    make_float2(acc[i][j][0] + b0, acc[i][j][1] + b1);
                *(float2*)&C[(size_t)mhi * DIM + col] =
                    make_float2(acc[i][j][2] + b0, acc[i][j][3] + b1);
            }
        }
    }
}

// ---------------- tf32 tensor-core flash attention ----------------
// grid: (SEQ/64, BATCH*HEADS), 128 threads (4 warps). Warp owns 16 q rows.
// Q fragments live in registers for the whole kernel. Online softmax is
// warp-local (quad shfl only). P goes through smem for the PV mma.
#define SLD 68   // padded row stride for Ks/Vs/Ps

__global__ void __launch_bounds__(128)
attn_tc(const float* __restrict__ Q, const float* __restrict__ K,
        const float* __restrict__ V, float* __restrict__ AO)
{
    extern __shared__ float sm[];
    float* Ks = sm;                 // 64*SLD
    float* Vs = Ks + 64 * SLD;      // 64*SLD
    float* Ps = Vs + 64 * SLD;      // 64*SLD

    const int tid  = threadIdx.x;
    const int warp = tid >> 5;
    const int lane = tid & 31;
    const int r    = lane >> 2;     // 0..7
    const int c    = lane & 3;      // 0..3
    const int wr   = warp * 16;     // warp's q-row base within tile
    const int bh   = blockIdx.y;
    const int q0   = blockIdx.x * 64;

    const float* Qg = Q + ((size_t)bh * SEQ + q0) * HDIM;
    const float* Kg = K + (size_t)bh * SEQ * HDIM;
    const float* Vg = V + (size_t)bh * SEQ * HDIM;

    // Q fragments (scale folded in), held in registers: 8 ksteps x 4 regs
    unsigned qf[8][4];
#pragma unroll
    for (int ks = 0; ks < 8; ks++) {
        const int kb = ks * 8;
        qf[ks][0] = __float_as_uint(tf32r(Qg[(wr + r    ) * HDIM + kb + c    ] * ATTN_SCALE));
        qf[ks][1] = __float_as_uint(tf32r(Qg[(wr + r + 8) * HDIM + kb + c    ] * ATTN_SCALE));
        qf[ks][2] = __float_as_uint(tf32r(Qg[(wr + r    ) * HDIM + kb + c + 4] * ATTN_SCALE));
        qf[ks][3] = __float_as_uint(tf32r(Qg[(wr + r + 8) * HDIM + kb + c + 4] * ATTN_SCALE));
    }

    float m_lo = -1e30f, m_hi = -1e30f, l_lo = 0.f, l_hi = 0.f;
    float o[8][4];
#pragma unroll
    for (int nt = 0; nt < 8; nt++)
#pragma unroll
        for (int t = 0; t < 4; t++) o[nt][t] = 0.f;

    for (int kt = 0; kt < SEQ; kt += 64) {
        __syncthreads();   // protect Ks/Vs from previous-iteration readers
        // load K/V tile (64x64), cvt to tf32
#pragma unroll
        for (int j = 0; j < 8; j++) {
            int id  = tid + j * 128;
            int row = id >> 4;
            int col = (id & 15) * 4;
            float4 kv = *(const float4*)&Kg[(size_t)(kt + row) * HDIM + col];
            float4 vv = *(const float4*)&Vg[(size_t)(kt + row) * HDIM + col];
            kv.x = tf32r(kv.x); kv.y = tf32r(kv.y); kv.z = tf32r(kv.z); kv.w = tf32r(kv.w);
            vv.x = tf32r(vv.x); vv.y = tf32r(vv.y); vv.z = tf32r(vv.z); vv.w = tf32r(vv.w);
            *(float4*)&Ks[row * SLD + col] = kv;
            *(float4*)&Vs[row * SLD + col] = vv;
        }
        __syncthreads();

        // ---- S = (Q*scale) K^T via mma ----
        float s[8][4];
#pragma unroll
        for (int nt = 0; nt < 8; nt++)
#pragma unroll
            for (int t = 0; t < 4; t++) s[nt][t] = 0.f;

#pragma unroll
        for (int ks = 0; ks < 8; ks++) {
            const int kb = ks * 8;
#pragma unroll
            for (int nt = 0; nt < 8; nt++) {
                unsigned b0 = __float_as_uint(Ks[(nt * 8 + r) * SLD + kb + c    ]);
                unsigned b1 = __float_as_uint(Ks[(nt * 8 + r) * SLD + kb + c + 4]);
                mma_tf32(s[nt], qf[ks][0], qf[ks][1], qf[ks][2], qf[ks][3], b0, b1);
            }
        }

        // ---- online softmax (warp-local: quad shuffle) ----
        float tl = -1e30f, th = -1e30f;
#pragma unroll
        for (int nt = 0; nt < 8; nt++) {
            tl = fmaxf(tl, fmaxf(s[nt][0], s[nt][1]));
            th = fmaxf(th, fmaxf(s[nt][2], s[nt][3]));
        }
        tl = fmaxf(tl, __shfl_xor_sync(0xffffffffu, tl, 1));
        tl = fmaxf(tl, __shfl_xor_sync(0xffffffffu, tl, 2));
        th = fmaxf(th, __shfl_xor_sync(0xffffffffu, th, 1));
        th = fmaxf(th, __shfl_xor_sync(0xffffffffu, th, 2));

        const float ml2 = fmaxf(m_lo, tl);
        const float mh2 = fmaxf(m_hi, th);
        const float al  = __expf(m_lo - ml2);
        const float ah  = __expf(m_hi - mh2);

        float pl = 0.f, ph = 0.f;
#pragma unroll
        for (int nt = 0; nt < 8; nt++) {
            float p0 = __expf(s[nt][0] - ml2);
            float p1 = __expf(s[nt][1] - ml2);
            float p2 = __expf(s[nt][2] - mh2);
            float p3 = __expf(s[nt][3] - mh2);
            pl += p0 + p1;
            ph += p2 + p3;
            *(float2*)&Ps[(wr + r    ) * SLD + nt * 8 + c * 2] =
                make_float2(tf32r(p0), tf32r(p1));
            *(float2*)&Ps[(wr + r + 8) * SLD + nt * 8 + c * 2] =
                make_float2(tf32r(p2), tf32r(p3));
        }
        pl += __shfl_xor_sync(0xffffffffu, pl, 1);
        pl += __shfl_xor_sync(0xffffffffu, pl, 2);
        ph += __shfl_xor_sync(0xffffffffu, ph, 1);
        ph += __shfl_xor_sync(0xffffffffu, ph, 2);

        l_lo = l_lo * al + pl;  m_lo = ml2;
        l_hi = l_hi * ah + ph;  m_hi = mh2;

#pragma unroll
        for (int nt = 0; nt < 8; nt++) {
            o[nt][0] *= al; o[nt][1] *= al;
            o[nt][2] *= ah; o[nt][3] *= ah;
        }
        __syncwarp();   // P strip is warp-private: warp-level sync suffices

        // ---- O += P V via mma ----
#pragma unroll
        for (int ks = 0; ks < 8; ks++) {
            const int kb = ks * 8;
            unsigned pa0 = __float_as_uint(Ps[(wr + r    ) * SLD + kb + c    ]);
            unsigned pa1 = __float_as_uint(Ps[(wr + r + 8) * SLD + kb + c    ]);
            unsigned pa2 = __float_as_uint(Ps[(wr + r    ) * SLD + kb + c + 4]);
            unsigned pa3 = __float_as_uint(Ps[(wr + r + 8) * SLD + kb + c + 4]);
#pragma unroll
            for (int nt = 0; nt < 8; nt++) {
                unsigned b0 = __float_as_uint(Vs[(kb + c    ) * SLD + nt * 8 + r]);
                unsigned b1 = __float_as_uint(Vs[(kb + c + 4) * SLD + nt * 8 + r]);
                mma_tf32(o[nt], pa0, pa1, pa2, pa3, b0, b1);
            }
        }
    }

    // epilogue: normalize, write [b][n][h*64+d]
    const float il = 1.0f / l_lo;
    const float ih = 1.0f / l_hi;
    const int b = bh >> 4;
    const int h = bh & 15;
    const int rlo = q0 + wr + r;
    const int rhi = rlo + 8;
    float* dlo = &g_AO[((size_t)(b * SEQ + rlo)) * DIM + h * HDIM];
    float* dhi = &g_AO[((size_t)(b * SEQ + rhi)) * DIM + h * HDIM];
#pragma unroll
    for (int nt = 0; nt < 8; nt++) {
        const int d0 = nt * 8 + c * 2;
        *(float2*)&dlo[d0] = make_float2(o[nt][0] * il, o[nt][1] * il);
        *(float2*)&dhi[d0] = make_float2(o[nt][2] * ih, o[nt][3] * ih);
    }
}

// ---------------- launch ----------------
extern "C" void kernel_launch(void* const* d_in, const int* in_sizes, int n_in,
                              void* d_out, int out_size)
{
    const float* x  = (const float*)d_in[0];
    const float* y  = (const float*)d_in[1];
    const float* Wq = (const float*)d_in[2];
    const float* Wk = (const float*)d_in[3];
    const float* Wv = (const float*)d_in[4];
    const float* Wp = (const float*)d_in[5];
    const float* bp = (const float*)d_in[6];
    float* out = (float*)d_out;

    float *qb, *kb, *vb, *ao;
    cudaGetSymbolAddress((void**)&qb, g_Q);
    cudaGetSymbolAddress((void**)&kb, g_K);
    cudaGetSymbolAddress((void**)&vb, g_V);
    cudaGetSymbolAddress((void**)&ao, g_AO);

    cudaFuncSetAttribute(gemm_tc<1>, cudaFuncAttributeMaxDynamicSharedMemorySize, GEMM_SMEM);
    cudaFuncSetAttribute(gemm_tc<0>, cudaFuncAttributeMaxDynamicSharedMemorySize, GEMM_SMEM);

    // QKV projections: one z-batched launch (z=0: x@Wq, z=1: y@Wk, z=2: y@Wv)
    GemmPtrs qkv;
    qkv.A[0] = x;  qkv.A[1] = y;  qkv.A[2] = y;
    qkv.B[0] = Wq; qkv.B[1] = Wk; qkv.B[2] = Wv;
    qkv.C[0] = qb; qkv.C[1] = kb; qkv.C[2] = vb;
    dim3 qkv_grid(DIM / 128, ROWS / 128, 3);   // (8, 32, 3) = 768 CTAs
    gemm_tc<1><<<qkv_grid, 256, GEMM_SMEM>>>(qkv, nullptr);

    const int smem = 3 * 64 * SLD * sizeof(float);   // 52224 bytes
    cudaFuncSetAttribute(attn_tc, cudaFuncAttributeMaxDynamicSharedMemorySize, smem);
    dim3 agrid(SEQ / 64, BATCH * HEADS);   // (32, 32)
    attn_tc<<<agrid, 128, smem>>>(qb, kb, vb, ao);

    // output projection
    GemmPtrs po;
    po.A[0] = ao; po.B[0] = Wp; po.C[0] = out;
    po.A[1] = po.A[2] = nullptr; po.B[1] = po.B[2] = nullptr; po.C[1] = po.C[2] = nullptr;
    dim3 ogrid(DIM / 128, ROWS / 128, 1);
    gemm_tc<0><<<ogrid, 256, GEMM_SMEM>>>(po, bp);
}

// round 10
// speedup vs baseline: 3.9953x; 1.0618x over previous
#include <cuda_runtime.h>
#include <cuda_bf16.h>

// Problem constants
#define BATCH   2
#define SEQ     2048
#define DIM     1024
#define HEADS   16
#define HDIM    64
#define ROWS    (BATCH * SEQ)          // 4096
#define ATTN_SCALE 0.125f              // 64^-0.5

// ---------------- scratch ----------------
__device__ float g_Q[BATCH * HEADS * SEQ * HDIM];   // [bh][n][d]
__device__ float g_K[BATCH * HEADS * SEQ * HDIM];
__device__ float g_V[BATCH * HEADS * SEQ * HDIM];
__device__ float g_AO[ROWS * DIM];                  // [b*SEQ+n][dim]

// ---------------- tf32 helpers ----------------
__device__ __forceinline__ float tf32r(float x) {
    unsigned u;
    asm("cvt.rna.tf32.f32 %0, %1;" : "=r"(u) : "f"(x));
    return __uint_as_float(u);
}
__device__ __forceinline__ unsigned tf32b(float x) {
    unsigned u;
    asm("cvt.rna.tf32.f32 %0, %1;" : "=r"(u) : "f"(x));
    return u;
}

__device__ __forceinline__ void mma_tf32(float c[4],
                                         unsigned a0, unsigned a1, unsigned a2, unsigned a3,
                                         unsigned b0, unsigned b1)
{
    asm("mma.sync.aligned.m16n8k8.row.col.f32.tf32.tf32.f32 "
        "{%0,%1,%2,%3}, {%4,%5,%6,%7}, {%8,%9}, {%0,%1,%2,%3};"
        : "+f"(c[0]), "+f"(c[1]), "+f"(c[2]), "+f"(c[3])
        : "r"(a0), "r"(a1), "r"(a2), "r"(a3), "r"(b0), "r"(b1));
}

// ---------------- cp.async helpers ----------------
__device__ __forceinline__ void cp_async16(void* smem_ptr, const void* gmem_ptr) {
    unsigned saddr = (unsigned)__cvta_generic_to_shared(smem_ptr);
    asm volatile("cp.async.ca.shared.global [%0], [%1], 16;"
                 :: "r"(saddr), "l"(gmem_ptr));
}
#define CP_COMMIT() asm volatile("cp.async.commit_group;" ::: "memory")
#define CP_WAIT1()  asm volatile("cp.async.wait_group 1;" ::: "memory")

struct GemmPtrs {
    const float* A[3];
    const float* B[3];
    float*       C[3];
};

// ---------------- tf32 tensor-core GEMM (unchanged from round 9) ----------------
#define AS_STAGE (128 * 36)
#define BS_STAGE (32 * 132)
#define GEMM_SMEM ((2 * AS_STAGE + 2 * BS_STAGE) * (int)sizeof(float))

template <int SPLIT_HEADS>
__global__ void __launch_bounds__(256, 2)
gemm_tc(GemmPtrs p, const float* __restrict__ bias)
{
    extern __shared__ float smem_g[];
    float* As = smem_g;                  // [2][128][36]
    float* Bs = smem_g + 2 * AS_STAGE;   // [2][32][132]

    const float* __restrict__ A = p.A[blockIdx.z];
    const float* __restrict__ B = p.B[blockIdx.z];
    float* __restrict__ C       = p.C[blockIdx.z];

    const int tid  = threadIdx.x;
    const int warp = tid >> 5;
    const int lane = tid & 31;
    const int r    = lane >> 2;
    const int c    = lane & 3;
    const int wm   = (warp & 3) * 32;
    const int wn   = (warp >> 2) * 64;
    const int row0 = blockIdx.y * 128;
    const int col0 = blockIdx.x * 128;

    int am[4], ak[4], bk[4], bn[4];
#pragma unroll
    for (int j = 0; j < 4; j++) {
        int id = tid + j * 256;
        am[j] = id >> 3;          ak[j] = (id & 7) * 4;
        bk[j] = id >> 5;          bn[j] = (id & 31) * 4;
    }

    float acc[2][8][4];
#pragma unroll
    for (int i = 0; i < 2; i++)
#pragma unroll
        for (int j = 0; j < 8; j++)
#pragma unroll
            for (int t = 0; t < 4; t++) acc[i][j][t] = 0.f;

    const int NT = DIM / 32;

#pragma unroll
    for (int s = 0; s < 2; s++) {
#pragma unroll
        for (int j = 0; j < 4; j++) {
            cp_async16(&As[s * AS_STAGE + am[j] * 36 + ak[j]],
                       &A[(size_t)(row0 + am[j]) * DIM + s * 32 + ak[j]]);
            cp_async16(&Bs[s * BS_STAGE + bk[j] * 132 + bn[j]],
                       &B[(size_t)(s * 32 + bk[j]) * DIM + col0 + bn[j]]);
        }
        CP_COMMIT();
    }

    for (int kt = 0; kt < NT; kt++) {
        const int st = kt & 1;
        CP_WAIT1();
        __syncthreads();

        const float* Asb = &As[st * AS_STAGE];
        const float* Bsb = &Bs[st * BS_STAGE];

#pragma unroll
        for (int ks = 0; ks < 4; ks++) {
            const int kb = ks * 8;
            unsigned a[2][4];
#pragma unroll
            for (int i = 0; i < 2; i++) {
                a[i][0] = tf32b(Asb[(wm + i * 16 + r    ) * 36 + kb + c    ]);
                a[i][1] = tf32b(Asb[(wm + i * 16 + r + 8) * 36 + kb + c    ]);
                a[i][2] = tf32b(Asb[(wm + i * 16 + r    ) * 36 + kb + c + 4]);
                a[i][3] = tf32b(Asb[(wm + i * 16 + r + 8) * 36 + kb + c + 4]);
            }
#pragma unroll
            for (int j = 0; j < 8; j++) {
                unsigned b0 = tf32b(Bsb[(kb + c    ) * 132 + wn + j * 8 + r]);
                unsigned b1 = tf32b(Bsb[(kb + c + 4) * 132 + wn + j * 8 + r]);
                mma_tf32(acc[0][j], a[0][0], a[0][1], a[0][2], a[0][3], b0, b1);
                mma_tf32(acc[1][j], a[1][0], a[1][1], a[1][2], a[1][3], b0, b1);
            }
        }
        __syncthreads();

        if (kt + 2 < NT) {
            const int k0 = (kt + 2) * 32;
#pragma unroll
            for (int j = 0; j < 4; j++) {
                cp_async16(&As[st * AS_STAGE + am[j] * 36 + ak[j]],
                           &A[(size_t)(row0 + am[j]) * DIM + k0 + ak[j]]);
                cp_async16(&Bs[st * BS_STAGE + bk[j] * 132 + bn[j]],
                           &B[(size_t)(k0 + bk[j]) * DIM + col0 + bn[j]]);
            }
        }
        CP_COMMIT();
    }

#pragma unroll
    for (int i = 0; i < 2; i++) {
#pragma unroll
        for (int j = 0; j < 8; j++) {
            const int mlo = row0 + wm + i * 16 + r;
            const int mhi = mlo + 8;
            const int col = col0 + wn + j * 8 + c * 2;
            if (SPLIT_HEADS) {
                const int h = col >> 6, d = col & 63;
                {
                    const int b = mlo >> 11, n = mlo & (SEQ - 1);
                    float* dst = &C[(((size_t)(b * HEADS + h) * SEQ + n) * HDIM) + d];
                    *(float2*)dst = make_float2(acc[i][j][0], acc[i][j][1]);
                }
                {
                    const int b = mhi >> 11, n = mhi & (SEQ - 1);
                    float* dst = &C[(((size_t)(b * HEADS + h) * SEQ + n) * HDIM) + d];
                    *(float2*)dst = make_float2(acc[i][j][2], acc[i][j][3]);
                }
            } else {
                const float b0 = bias[col], b1 = bias[col + 1];
                *(float2*)&C[(size_t)mlo * DIM + col] =
                    make_float2(acc[i][j][0] + b0, acc[i][j][1] + b1);
                *(float2*)&C[(size_t)mhi * DIM + col] =
                    make_float2(acc[i][j][2] + b0, acc[i][j][3] + b1);
            }
        }
    }
}

// ---------------- tf32 tensor-core flash attention ----------------
// grid: (SEQ/128, BATCH*HEADS), 128 threads (4 warps).
// Each warp owns 32 q-rows (two m16 tiles) -> K/V fragment loads amortized 2x.
// CTA q-tile = 128 rows; KV tile = 64. Q fragments in registers throughout.
// Softmax warp-local (quad shfl). P via warp-private smem strips.
#define SLD 68   // padded row stride for Ks/Vs/Ps
#define ATTN_SMEM ((64 * SLD + 64 * SLD + 128 * SLD) * (int)sizeof(float))

__global__ void __launch_bounds__(128, 2)
attn_tc(const float* __restrict__ Q, const float* __restrict__ K,
        const float* __restrict__ V, float* __restrict__ AO)
{
    extern __shared__ float sm[];
    float* Ks = sm;                 // 64*SLD
    float* Vs = Ks + 64 * SLD;      // 64*SLD
    float* Ps = Vs + 64 * SLD;      // 128*SLD

    const int tid  = threadIdx.x;
    const int warp = tid >> 5;
    const int lane = tid & 31;
    const int r    = lane >> 2;     // 0..7
    const int c    = lane & 3;      // 0..3
    const int wr   = warp * 32;     // warp's q-row base within 128-row tile
    const int bh   = blockIdx.y;
    const int q0   = blockIdx.x * 128;

    const float* Qg = Q + ((size_t)bh * SEQ + q0) * HDIM;
    const float* Kg = K + (size_t)bh * SEQ * HDIM;
    const float* Vg = V + (size_t)bh * SEQ * HDIM;

    // Q fragments (scale folded in): 2 m-tiles x 8 ksteps x 4 regs = 64 regs
    unsigned qf[2][8][4];
#pragma unroll
    for (int i = 0; i < 2; i++) {
        const int rb = wr + i * 16;
#pragma unroll
        for (int ks = 0; ks < 8; ks++) {
            const int kb = ks * 8;
            qf[i][ks][0] = tf32b(Qg[(rb + r    ) * HDIM + kb + c    ] * ATTN_SCALE);
            qf[i][ks][1] = tf32b(Qg[(rb + r + 8) * HDIM + kb + c    ] * ATTN_SCALE);
            qf[i][ks][2] = tf32b(Qg[(rb + r    ) * HDIM + kb + c + 4] * ATTN_SCALE);
            qf[i][ks][3] = tf32b(Qg[(rb + r + 8) * HDIM + kb + c + 4] * ATTN_SCALE);
        }
    }

    // per m-tile row stats: [i][0]=row r ("lo"), [i][1]=row r+8 ("hi")
    float mst[2][2] = {{-1e30f, -1e30f}, {-1e30f, -1e30f}};
    float lst[2][2] = {{0.f, 0.f}, {0.f, 0.f}};
    float o[2][8][4];
#pragma unroll
    for (int i = 0; i < 2; i++)
#pragma unroll
        for (int nt = 0; nt < 8; nt++)
#pragma unroll
            for (int t = 0; t < 4; t++) o[i][nt][t] = 0.f;

    for (int kt = 0; kt < SEQ; kt += 64) {
        __syncthreads();   // protect shared Ks/Vs from previous-iteration readers
        // load K/V tile (64x64), cvt.rna to tf32
#pragma unroll
        for (int j = 0; j < 8; j++) {
            int id  = tid + j * 128;
            int row = id >> 4;
            int col = (id & 15) * 4;
            float4 kv = *(const float4*)&Kg[(size_t)(kt + row) * HDIM + col];
            float4 vv = *(const float4*)&Vg[(size_t)(kt + row) * HDIM + col];
            kv.x = tf32r(kv.x); kv.y = tf32r(kv.y); kv.z = tf32r(kv.z); kv.w = tf32r(kv.w);
            vv.x = tf32r(vv.x); vv.y = tf32r(vv.y); vv.z = tf32r(vv.z); vv.w = tf32r(vv.w);
            *(float4*)&Ks[row * SLD + col] = kv;
            *(float4*)&Vs[row * SLD + col] = vv;
        }
        __syncthreads();

        // ---- S = (Q*scale) K^T via mma: K frag loaded once, used by both m-tiles ----
        float s[2][8][4];
#pragma unroll
        for (int i = 0; i < 2; i++)
#pragma unroll
            for (int nt = 0; nt < 8; nt++)
#pragma unroll
                for (int t = 0; t < 4; t++) s[i][nt][t] = 0.f;

#pragma unroll
        for (int ks = 0; ks < 8; ks++) {
            const int kb = ks * 8;
#pragma unroll
            for (int nt = 0; nt < 8; nt++) {
                unsigned b0 = __float_as_uint(Ks[(nt * 8 + r) * SLD + kb + c    ]);
                unsigned b1 = __float_as_uint(Ks[(nt * 8 + r) * SLD + kb + c + 4]);
                mma_tf32(s[0][nt], qf[0][ks][0], qf[0][ks][1], qf[0][ks][2], qf[0][ks][3], b0, b1);
                mma_tf32(s[1][nt], qf[1][ks][0], qf[1][ks][1], qf[1][ks][2], qf[1][ks][3], b0, b1);
            }
        }

        // ---- online softmax (warp-local: quad shuffle), per m-tile ----
        float alpha[2][2];
#pragma unroll
        for (int i = 0; i < 2; i++) {
            float tl = -1e30f, th = -1e30f;
#pragma unroll
            for (int nt = 0; nt < 8; nt++) {
                tl = fmaxf(tl, fmaxf(s[i][nt][0], s[i][nt][1]));
                th = fmaxf(th, fmaxf(s[i][nt][2], s[i][nt][3]));
            }
            tl = fmaxf(tl, __shfl_xor_sync(0xffffffffu, tl, 1));
            tl = fmaxf(tl, __shfl_xor_sync(0xffffffffu, tl, 2));
            th = fmaxf(th, __shfl_xor_sync(0xffffffffu, th, 1));
            th = fmaxf(th, __shfl_xor_sync(0xffffffffu, th, 2));

            const float ml2 = fmaxf(mst[i][0], tl);
            const float mh2 = fmaxf(mst[i][1], th);
            alpha[i][0] = __expf(mst[i][0] - ml2);
            alpha[i][1] = __expf(mst[i][1] - mh2);

            float pl = 0.f, ph = 0.f;
            const int rb = wr + i * 16;
#pragma unroll
            for (int nt = 0; nt < 8; nt++) {
                float p0 = __expf(s[i][nt][0] - ml2);
                float p1 = __expf(s[i][nt][1] - ml2);
                float p2 = __expf(s[i][nt][2] - mh2);
                float p3 = __expf(s[i][nt][3] - mh2);
                pl += p0 + p1;
                ph += p2 + p3;
                *(float2*)&Ps[(rb + r    ) * SLD + nt * 8 + c * 2] =
                    make_float2(tf32r(p0), tf32r(p1));
                *(float2*)&Ps[(rb + r + 8) * SLD + nt * 8 + c * 2] =
                    make_float2(tf32r(p2), tf32r(p3));
            }
            pl += __shfl_xor_sync(0xffffffffu, pl, 1);
            pl += __shfl_xor_sync(0xffffffffu, pl, 2);
            ph += __shfl_xor_sync(0xffffffffu, ph, 1);
            ph += __shfl_xor_sync(0xffffffffu, ph, 2);

            lst[i][0] = lst[i][0] * alpha[i][0] + pl;  mst[i][0] = ml2;
            lst[i][1] = lst[i][1] * alpha[i][1] + ph;  mst[i][1] = mh2;

#pragma unroll
            for (int nt = 0; nt < 8; nt++) {
                o[i][nt][0] *= alpha[i][0]; o[i][nt][1] *= alpha[i][0];
                o[i][nt][2] *= alpha[i][1]; o[i][nt][3] *= alpha[i][1];
            }
        }
        __syncwarp();   // P strips are warp-private (rows wr..wr+31)

        // ---- O += P V via mma: V frag loaded once, used by both m-tiles ----
#pragma unroll
        for (int ks = 0; ks < 8; ks++) {
            const int kb = ks * 8;
            unsigned pa[2][4];
#pragma unroll
            for (int i = 0; i < 2; i++) {
                const int rb = wr + i * 16;
                pa[i][0] = __float_as_uint(Ps[(rb + r    ) * SLD + kb + c    ]);
                pa[i][1] = __float_as_uint(Ps[(rb + r + 8) * SLD + kb + c    ]);
                pa[i][2] = __float_as_uint(Ps[(rb + r    ) * SLD + kb + c + 4]);
                pa[i][3] = __float_as_uint(Ps[(rb + r + 8) * SLD + kb + c + 4]);
            }
#pragma unroll
            for (int nt = 0; nt < 8; nt++) {
                unsigned b0 = __float_as_uint(Vs[(kb + c    ) * SLD + nt * 8 + r]);
                unsigned b1 = __float_as_uint(Vs[(kb + c + 4) * SLD + nt * 8 + r]);
                mma_tf32(o[0][nt], pa[0][0], pa[0][1], pa[0][2], pa[0][3], b0, b1);
                mma_tf32(o[1][nt], pa[1][0], pa[1][1], pa[1][2], pa[1][3], b0, b1);
            }
        }
    }

    // epilogue: normalize, write [b][n][h*64+d]
    const int b = bh >> 4;
    const int h = bh & 15;
#pragma unroll
    for (int i = 0; i < 2; i++) {
        const float il = 1.0f / lst[i][0];
        const float ih = 1.0f / lst[i][1];
        const int rlo = q0 + wr + i * 16 + r;
        const int rhi = rlo + 8;
        float* dlo = &g_AO[((size_t)(b * SEQ + rlo)) * DIM + h * HDIM];
        float* dhi = &g_AO[((size_t)(b * SEQ + rhi)) * DIM + h * HDIM];
#pragma unroll
        for (int nt = 0; nt < 8; nt++) {
            const int d0 = nt * 8 + c * 2;
            *(float2*)&dlo[d0] = make_float2(o[i][nt][0] * il, o[i][nt][1] * il);
            *(float2*)&dhi[d0] = make_float2(o[i][nt][2] * ih, o[i][nt][3] * ih);
        }
    }
}

// ---------------- launch ----------------
extern "C" void kernel_launch(void* const* d_in, const int* in_sizes, int n_in,
                              void* d_out, int out_size)
{
    const float* x  = (const float*)d_in[0];
    const float* y  = (const float*)d_in[1];
    const float* Wq = (const float*)d_in[2];
    const float* Wk = (const float*)d_in[3];
    const float* Wv = (const float*)d_in[4];
    const float* Wp = (const float*)d_in[5];
    const float* bp = (const float*)d_in[6];
    float* out = (float*)d_out;

    float *qb, *kb, *vb, *ao;
    cudaGetSymbolAddress((void**)&qb, g_Q);
    cudaGetSymbolAddress((void**)&kb, g_K);
    cudaGetSymbolAddress((void**)&vb, g_V);
    cudaGetSymbolAddress((void**)&ao, g_AO);

    cudaFuncSetAttribute(gemm_tc<1>, cudaFuncAttributeMaxDynamicSharedMemorySize, GEMM_SMEM);
    cudaFuncSetAttribute(gemm_tc<0>, cudaFuncAttributeMaxDynamicSharedMemorySize, GEMM_SMEM);
    cudaFuncSetAttribute(attn_tc,    cudaFuncAttributeMaxDynamicSharedMemorySize, ATTN_SMEM);

    // QKV projections: one z-batched launch (z=0: x@Wq, z=1: y@Wk, z=2: y@Wv)
    GemmPtrs qkv;
    qkv.A[0] = x;  qkv.A[1] = y;  qkv.A[2] = y;
    qkv.B[0] = Wq; qkv.B[1] = Wk; qkv.B[2] = Wv;
    qkv.C[0] = qb; qkv.C[1] = kb; qkv.C[2] = vb;
    dim3 qkv_grid(DIM / 128, ROWS / 128, 3);   // (8, 32, 3) = 768 CTAs
    gemm_tc<1><<<qkv_grid, 256, GEMM_SMEM>>>(qkv, nullptr);

    dim3 agrid(SEQ / 128, BATCH * HEADS);      // (16, 32) = 512 CTAs
    attn_tc<<<agrid, 128, ATTN_SMEM>>>(qb, kb, vb, ao);

    // output projection
    GemmPtrs po;
    po.A[0] = ao; po.B[0] = Wp; po.C[0] = out;
    po.A[1] = po.A[2] = nullptr; po.B[1] = po.B[2] = nullptr; po.C[1] = po.C[2] = nullptr;
    dim3 ogrid(DIM / 128, ROWS / 128, 1);
    gemm_tc<0><<<ogrid, 256, GEMM_SMEM>>>(po, bp);
}

// round 12
// speedup vs baseline: 4.3175x; 1.0806x over previous
#include <cuda_runtime.h>
#include <cuda_bf16.h>

// Problem constants
#define BATCH   2
#define SEQ     2048
#define DIM     1024
#define HEADS   16
#define HDIM    64
#define ROWS    (BATCH * SEQ)          // 4096
#define ATTN_SCALE 0.125f              // 64^-0.5

// ---------------- scratch ----------------
__device__ float g_Q[BATCH * HEADS * SEQ * HDIM];   // [bh][n][d]
__device__ float g_K[BATCH * HEADS * SEQ * HDIM];
__device__ float g_V[BATCH * HEADS * SEQ * HDIM];
__device__ float g_AO[ROWS * DIM];                  // [b*SEQ+n][dim]

// ---------------- tf32 helpers ----------------
__device__ __forceinline__ float tf32r(float x) {
    unsigned u;
    asm("cvt.rna.tf32.f32 %0, %1;" : "=r"(u) : "f"(x));
    return __uint_as_float(u);
}
__device__ __forceinline__ unsigned tf32b(float x) {
    unsigned u;
    asm("cvt.rna.tf32.f32 %0, %1;" : "=r"(u) : "f"(x));
    return u;
}

__device__ __forceinline__ void mma_tf32(float c[4],
                                         unsigned a0, unsigned a1, unsigned a2, unsigned a3,
                                         unsigned b0, unsigned b1)
{
    asm("mma.sync.aligned.m16n8k8.row.col.f32.tf32.tf32.f32 "
        "{%0,%1,%2,%3}, {%4,%5,%6,%7}, {%8,%9}, {%0,%1,%2,%3};"
        : "+f"(c[0]), "+f"(c[1]), "+f"(c[2]), "+f"(c[3])
        : "r"(a0), "r"(a1), "r"(a2), "r"(a3), "r"(b0), "r"(b1));
}

// ---------------- cp.async helpers ----------------
__device__ __forceinline__ void cp_async16(void* smem_ptr, const void* gmem_ptr) {
    unsigned saddr = (unsigned)__cvta_generic_to_shared(smem_ptr);
    asm volatile("cp.async.ca.shared.global [%0], [%1], 16;"
                 :: "r"(saddr), "l"(gmem_ptr));
}
#define CP_COMMIT() asm volatile("cp.async.commit_group;" ::: "memory")
#define CP_WAIT1()  asm volatile("cp.async.wait_group 1;" ::: "memory")

struct GemmPtrs {
    const float* A[3];
    const float* B[3];
    float*       C[3];
};

// ---------------- tf32 tensor-core GEMM ----------------
// Block tile 128x128, BK=32. 128 threads, 4 warps of 64x64 each
// (warp_m = warp&1, warp_n = warp>>1). LDS bytes/mma: 192 -> 128 (crossbar parity).
// 2-stage cp.async double buffer, raw fp32 in smem, cvt.rna at fragment load.
#define AS_STAGE (128 * 36)
#define BS_STAGE (32 * 132)
#define GEMM_SMEM ((2 * AS_STAGE + 2 * BS_STAGE) * (int)sizeof(float))

template <int SPLIT_HEADS>
__global__ void __launch_bounds__(128, 2)
gemm_tc(GemmPtrs p, const float* __restrict__ bias)
{
    extern __shared__ float smem_g[];
    float* As = smem_g;                  // [2][128][36]
    float* Bs = smem_g + 2 * AS_STAGE;   // [2][32][132]

    const float* __restrict__ A = p.A[blockIdx.z];
    const float* __restrict__ B = p.B[blockIdx.z];
    float* __restrict__ C       = p.C[blockIdx.z];

    const int tid  = threadIdx.x;
    const int warp = tid >> 5;        // 0..3
    const int lane = tid & 31;
    const int r    = lane >> 2;       // 0..7
    const int c    = lane & 3;        // 0..3
    const int wm   = (warp & 1) * 64;
    const int wn   = (warp >> 1) * 64;
    const int row0 = blockIdx.y * 128;
    const int col0 = blockIdx.x * 128;

    // loader coordinates: 8 A-chunks + 8 B-chunks per thread per stage.
    // A chunk j: row a_m0 + 16j, cols a_k4..a_k4+3. B chunk j: row b_k0 + 4j, cols b_n4..+3.
    const int a_m0 = tid >> 3;          // 0..15
    const int a_k4 = (tid & 7) * 4;     // 0..28
    const int b_k0 = tid >> 5;          // 0..3
    const int b_n4 = (tid & 31) * 4;    // 0..124

    float acc[4][8][4];
#pragma unroll
    for (int i = 0; i < 4; i++)
#pragma unroll
        for (int j = 0; j < 8; j++)
#pragma unroll
            for (int t = 0; t < 4; t++) acc[i][j][t] = 0.f;

    const int NT = DIM / 32;   // 32 k-tiles

    // prologue: async-load k-tiles 0 and 1
#pragma unroll
    for (int s = 0; s < 2; s++) {
#pragma unroll
        for (int j = 0; j < 8; j++) {
            cp_async16(&As[s * AS_STAGE + (a_m0 + j * 16) * 36 + a_k4],
                       &A[(size_t)(row0 + a_m0 + j * 16) * DIM + s * 32 + a_k4]);
            cp_async16(&Bs[s * BS_STAGE + (b_k0 + j * 4) * 132 + b_n4],
                       &B[(size_t)(s * 32 + b_k0 + j * 4) * DIM + col0 + b_n4]);
        }
        CP_COMMIT();
    }

    for (int kt = 0; kt < NT; kt++) {
        const int st = kt & 1;
        CP_WAIT1();
        __syncthreads();

        const float* Asb = &As[st * AS_STAGE];
        const float* Bsb = &Bs[st * BS_STAGE];

#pragma unroll
        for (int ks = 0; ks < 4; ks++) {
            const int kb = ks * 8;
            unsigned a[4][4];
#pragma unroll
            for (int i = 0; i < 4; i++) {
                a[i][0] = tf32b(Asb[(wm + i * 16 + r    ) * 36 + kb + c    ]);
                a[i][1] = tf32b(Asb[(wm + i * 16 + r + 8) * 36 + kb + c    ]);
                a[i][2] = tf32b(Asb[(wm + i * 16 + r    ) * 36 + kb + c + 4]);
                a[i][3] = tf32b(Asb[(wm + i * 16 + r + 8) * 36 + kb + c + 4]);
            }
#pragma unroll
            for (int j = 0; j < 8; j++) {
                unsigned b0 = tf32b(Bsb[(kb + c    ) * 132 + wn + j * 8 + r]);
                unsigned b1 = tf32b(Bsb[(kb + c + 4) * 132 + wn + j * 8 + r]);
#pragma unroll
                for (int i = 0; i < 4; i++)
                    mma_tf32(acc[i][j], a[i][0], a[i][1], a[i][2], a[i][3], b0, b1);
            }
        }
        __syncthreads();

        if (kt + 2 < NT) {
            const int k0 = (kt + 2) * 32;
#pragma unroll
            for (int j = 0; j < 8; j++) {
                cp_async16(&As[st * AS_STAGE + (a_m0 + j * 16) * 36 + a_k4],
                           &A[(size_t)(row0 + a_m0 + j * 16) * DIM + k0 + a_k4]);
                cp_async16(&Bs[st * BS_STAGE + (b_k0 + j * 4) * 132 + b_n4],
                           &B[(size_t)(k0 + b_k0 + j * 4) * DIM + col0 + b_n4]);
            }
        }
        CP_COMMIT();
    }

    // epilogue
#pragma unroll
    for (int i = 0; i < 4; i++) {
#pragma unroll
        for (int j = 0; j < 8; j++) {
            const int mlo = row0 + wm + i * 16 + r;
            const int mhi = mlo + 8;
            const int col = col0 + wn + j * 8 + c * 2;
            if (SPLIT_HEADS) {
                const int h = col >> 6, d = col & 63;
                {
                    const int b = mlo >> 11, n = mlo & (SEQ - 1);
                    float* dst = &C[(((size_t)(b * HEADS + h) * SEQ + n) * HDIM) + d];
                    *(float2*)dst = make_float2(acc[i][j][0], acc[i][j][1]);
                }
                {
                    const int b = mhi >> 11, n = mhi & (SEQ - 1);
                    float* dst = &C[(((size_t)(b * HEADS + h) * SEQ + n) * HDIM) + d];
                    *(float2*)dst = make_float2(acc[i][j][2], acc[i][j][3]);
                }
            } else {
                const float b0 = bias[col], b1 = bias[col + 1];
                *(float2*)&C[(size_t)mlo * DIM + col] =
                    make_float2(acc[i][j][0] + b0, acc[i][j][1] + b1);
                *(float2*)&C[(size_t)mhi * DIM + col] =
                    make_float2(acc[i][j][2] + b0, acc[i][j][3] + b1);
            }
        }
    }
}

// ---------------- tf32 tensor-core flash attention ----------------
// grid: (SEQ/128, BATCH*HEADS), 128 threads (4 warps); warp owns 32 q-rows.
// K/V tiles: 2-stage cp.async double buffer (raw fp32 in smem, cvt at fragment
// load — numerically identical). Q fragments in registers throughout.
#define SLD 68                       // padded row stride (16B-aligned rows)
#define KV_STAGE (64 * SLD)
#define ATTN_SMEM ((4 * KV_STAGE + 128 * SLD) * (int)sizeof(float))   // 104448 B

__global__ void __launch_bounds__(128, 2)
attn_tc(const float* __restrict__ Q, const float* __restrict__ K,
        const float* __restrict__ V, float* __restrict__ AO)
{
    extern __shared__ float sm[];
    float* KsB = sm;                     // [2][64*SLD]
    float* VsB = sm + 2 * KV_STAGE;      // [2][64*SLD]
    float* Ps  = sm + 4 * KV_STAGE;      // [128*SLD]

    const int tid  = threadIdx.x;
    const int warp = tid >> 5;
    const int lane = tid & 31;
    const int r    = lane >> 2;     // 0..7
    const int c    = lane & 3;      // 0..3
    const int wr   = warp * 32;     // warp's q-row base within 128-row tile
    const int bh   = blockIdx.y;
    const int q0   = blockIdx.x * 128;

    const float* Qg = Q + ((size_t)bh * SEQ + q0) * HDIM;
    const float* Kg = K + (size_t)bh * SEQ * HDIM;
    const float* Vg = V + (size_t)bh * SEQ * HDIM;

    // loader coords: per stage, 8 K-chunks + 8 V-chunks per thread
    const int l_r0 = tid >> 4;          // 0..7
    const int l_c4 = (tid & 15) * 4;    // 0..60

    // Q fragments (scale folded in): 2 m-tiles x 8 ksteps x 4 regs
    unsigned qf[2][8][4];
#pragma unroll
    for (int i = 0; i < 2; i++) {
        const int rb = wr + i * 16;
#pragma unroll
        for (int ks = 0; ks < 8; ks++) {
            const int kb = ks * 8;
            qf[i][ks][0] = tf32b(Qg[(rb + r    ) * HDIM + kb + c    ] * ATTN_SCALE);
            qf[i][ks][1] = tf32b(Qg[(rb + r + 8) * HDIM + kb + c    ] * ATTN_SCALE);
            qf[i][ks][2] = tf32b(Qg[(rb + r    ) * HDIM + kb + c + 4] * ATTN_SCALE);
            qf[i][ks][3] = tf32b(Qg[(rb + r + 8) * HDIM + kb + c + 4] * ATTN_SCALE);
        }
    }

    float mst[2][2] = {{-1e30f, -1e30f}, {-1e30f, -1e30f}};
    float lst[2][2] = {{0.f, 0.f}, {0.f, 0.f}};
    float o[2][8][4];
#pragma unroll
    for (int i = 0; i < 2; i++)
#pragma unroll
        for (int nt = 0; nt < 8; nt++)
#pragma unroll
            for (int t = 0; t < 4; t++) o[i][nt][t] = 0.f;

    const int NKT = SEQ / 64;   // 32 KV tiles

    // prologue: async-load KV tiles 0 and 1
#pragma unroll
    for (int s = 0; s < 2; s++) {
#pragma unroll
        for (int j = 0; j < 8; j++) {
            const int row = l_r0 + j * 8;
            cp_async16(&KsB[s * KV_STAGE + row * SLD + l_c4],
                       &Kg[(size_t)(s * 64 + row) * HDIM + l_c4]);
            cp_async16(&VsB[s * KV_STAGE + row * SLD + l_c4],
                       &Vg[(size_t)(s * 64 + row) * HDIM + l_c4]);
        }
        CP_COMMIT();
    }

    for (int t = 0; t < NKT; t++) {
        const int st = t & 1;
        CP_WAIT1();
        __syncthreads();

        const float* Ks = &KsB[st * KV_STAGE];
        const float* Vs = &VsB[st * KV_STAGE];

        // ---- S = (Q*scale) K^T via mma (cvt.rna at fragment load) ----
        float s[2][8][4];
#pragma unroll
        for (int i = 0; i < 2; i++)
#pragma unroll
            for (int nt = 0; nt < 8; nt++)
#pragma unroll
                for (int tt = 0; tt < 4; tt++) s[i][nt][tt] = 0.f;

#pragma unroll
        for (int ks = 0; ks < 8; ks++) {
            const int kb = ks * 8;
#pragma unroll
            for (int nt = 0; nt < 8; nt++) {
                unsigned b0 = tf32b(Ks[(nt * 8 + r) * SLD + kb + c    ]);
                unsigned b1 = tf32b(Ks[(nt * 8 + r) * SLD + kb + c + 4]);
                mma_tf32(s[0][nt], qf[0][ks][0], qf[0][ks][1], qf[0][ks][2], qf[0][ks][3], b0, b1);
                mma_tf32(s[1][nt], qf[1][ks][0], qf[1][ks][1], qf[1][ks][2], qf[1][ks][3], b0, b1);
            }
        }

        // ---- online softmax (warp-local quad shuffle), per m-tile ----
        float alpha[2][2];
#pragma unroll
        for (int i = 0; i < 2; i++) {
            float tl = -1e30f, th = -1e30f;
#pragma unroll
            for (int nt = 0; nt < 8; nt++) {
                tl = fmaxf(tl, fmaxf(s[i][nt][0], s[i][nt][1]));
                th = fmaxf(th, fmaxf(s[i][nt][2], s[i][nt][3]));
            }
            tl = fmaxf(tl, __shfl_xor_sync(0xffffffffu, tl, 1));
            tl = fmaxf(tl, __shfl_xor_sync(0xffffffffu, tl, 2));
            th = fmaxf(th, __shfl_xor_sync(0xffffffffu, th, 1));
            th = fmaxf(th, __shfl_xor_sync(0xffffffffu, th, 2));

            const float ml2 = fmaxf(mst[i][0], tl);
            const float mh2 = fmaxf(mst[i][1], th);
            alpha[i][0] = __expf(mst[i][0] - ml2);
            alpha[i][1] = __expf(mst[i][1] - mh2);

            float pl = 0.f, ph = 0.f;
            const int rb = wr + i * 16;
#pragma unroll
            for (int nt = 0; nt < 8; nt++) {
                float p0 = __expf(s[i][nt][0] - ml2);
                float p1 = __expf(s[i][nt][1] - ml2);
                float p2 = __expf(s[i][nt][2] - mh2);
                float p3 = __expf(s[i][nt][3] - mh2);
                pl += p0 + p1;
                ph += p2 + p3;
                *(float2*)&Ps[(rb + r    ) * SLD + nt * 8 + c * 2] =
                    make_float2(tf32r(p0), tf32r(p1));
                *(float2*)&Ps[(rb + r + 8) * SLD + nt * 8 + c * 2] =
                    make_float2(tf32r(p2), tf32r(p3));
            }
            pl += __shfl_xor_sync(0xffffffffu, pl, 1);
            pl += __shfl_xor_sync(0xffffffffu, pl, 2);
            ph += __shfl_xor_sync(0xffffffffu, ph, 1);
            ph += __shfl_xor_sync(0xffffffffu, ph, 2);

            lst[i][0] = lst[i][0] * alpha[i][0] + pl;  mst[i][0] = ml2;
            lst[i][1] = lst[i][1] * alpha[i][1] + ph;  mst[i][1] = mh2;

#pragma unroll
            for (int nt = 0; nt < 8; nt++) {
                o[i][nt][0] *= alpha[i][0]; o[i][nt][1] *= alpha[i][0];
                o[i][nt][2] *= alpha[i][1]; o[i][nt][3] *= alpha[i][1];
            }
        }
        __syncwarp();   // P strips are warp-private (rows wr..wr+31)

        // ---- O += P V via mma ----
#pragma unroll
        for (int ks = 0; ks < 8; ks++) {
            const int kb = ks * 8;
            unsigned pa[2][4];
#pragma unroll
            for (int i = 0; i < 2; i++) {
                const int rb = wr + i * 16;
                pa[i][0] = __float_as_uint(Ps[(rb + r    ) * SLD + kb + c    ]);
                pa[i][1] = __float_as_uint(Ps[(rb + r + 8) * SLD + kb + c    ]);
                pa[i][2] = __float_as_uint(Ps[(rb + r    ) * SLD + kb + c + 4]);
                pa[i][3] = __float_as_uint(Ps[(rb + r + 8) * SLD + kb + c + 4]);
            }
#pragma unroll
            for (int nt = 0; nt < 8; nt++) {
                unsigned b0 = tf32b(Vs[(kb + c    ) * SLD + nt * 8 + r]);
                unsigned b1 = tf32b(Vs[(kb + c + 4) * SLD + nt * 8 + r]);
                mma_tf32(o[0][nt], pa[0][0], pa[0][1], pa[0][2], pa[0][3], b0, b1);
                mma_tf32(o[1][nt], pa[1][0], pa[1][1], pa[1][2], pa[1][3], b0, b1);
            }
        }
        __syncthreads();   // all warps done with stage st before overwrite

        if (t + 2 < NKT) {
            const int kt2 = (t + 2) * 64;
#pragma unroll
            for (int j = 0; j < 8; j++) {
                const int row = l_r0 + j * 8;
                cp_async16(&KsB[st * KV_STAGE + row * SLD + l_c4],
                           &Kg[(size_t)(kt2 + row) * HDIM + l_c4]);
                cp_async16(&VsB[st * KV_STAGE + row * SLD + l_c4],
                           &Vg[(size_t)(kt2 + row) * HDIM + l_c4]);
            }
        }
        CP_COMMIT();
    }

    // epilogue: normalize, write [b][n][h*64+d]
    const int b = bh >> 4;
    const int h = bh & 15;
#pragma unroll
    for (int i = 0; i < 2; i++) {
        const float il = 1.0f / lst[i][0];
        const float ih = 1.0f / lst[i][1];
        const int rlo = q0 + wr + i * 16 + r;
        const int rhi = rlo + 8;
        float* dlo = &g_AO[((size_t)(b * SEQ + rlo)) * DIM + h * HDIM];
        float* dhi = &g_AO[((size_t)(b * SEQ + rhi)) * DIM + h * HDIM];
#pragma unroll
        for (int nt = 0; nt < 8; nt++) {
            const int d0 = nt * 8 + c * 2;
            *(float2*)&dlo[d0] = make_float2(o[i][nt][0] * il, o[i][nt][1] * il);
            *(float2*)&dhi[d0] = make_float2(o[i][nt][2] * ih, o[i][nt][3] * ih);
        }
    }
}

// ---------------- launch ----------------
extern "C" void kernel_launch(void* const* d_in, const int* in_sizes, int n_in,
                              void* d_out, int out_size)
{
    const float* x  = (const float*)d_in[0];
    const float* y  = (const float*)d_in[1];
    const float* Wq = (const float*)d_in[2];
    const float* Wk = (const float*)d_in[3];
    const float* Wv = (const float*)d_in[4];
    const float* Wp = (const float*)d_in[5];
    const float* bp = (const float*)d_in[6];
    float* out = (float*)d_out;

    float *qb, *kb, *vb, *ao;
    cudaGetSymbolAddress((void**)&qb, g_Q);
    cudaGetSymbolAddress((void**)&kb, g_K);
    cudaGetSymbolAddress((void**)&vb, g_V);
    cudaGetSymbolAddress((void**)&ao, g_AO);

    cudaFuncSetAttribute(gemm_tc<1>, cudaFuncAttributeMaxDynamicSharedMemorySize, GEMM_SMEM);
    cudaFuncSetAttribute(gemm_tc<0>, cudaFuncAttributeMaxDynamicSharedMemorySize, GEMM_SMEM);
    cudaFuncSetAttribute(attn_tc,    cudaFuncAttributeMaxDynamicSharedMemorySize, ATTN_SMEM);

    // QKV projections: one z-batched launch (z=0: x@Wq, z=1: y@Wk, z=2: y@Wv)
    GemmPtrs qkv;
    qkv.A[0] = x;  qkv.A[1] = y;  qkv.A[2] = y;
    qkv.B[0] = Wq; qkv.B[1] = Wk; qkv.B[2] = Wv;
    qkv.C[0] = qb; qkv.C[1] = kb; qkv.C[2] = vb;
    dim3 qkv_grid(DIM / 128, ROWS / 128, 3);   // (8, 32, 3) = 768 CTAs
    gemm_tc<1><<<qkv_grid, 128, GEMM_SMEM>>>(qkv, nullptr);

    dim3 agrid(SEQ / 128, BATCH * HEADS);      // (16, 32) = 512 CTAs
    attn_tc<<<agrid, 128, ATTN_SMEM>>>(qb, kb, vb, ao);

    // output projection
    GemmPtrs po;
    po.A[0] = ao; po.B[0] = Wp; po.C[0] = out;
    po.A[1] = po.A[2] = nullptr; po.B[1] = po.B[2] = nullptr; po.C[1] = po.C[2] = nullptr;
    dim3 ogrid(DIM / 128, ROWS / 128, 1);
    gemm_tc<0><<<ogrid, 128, GEMM_SMEM>>>(po, bp);
}